// round 2
// baseline (speedup 1.0000x reference)
#include <cuda_runtime.h>
#include <math_constants.h>

#define NN 100000
#define DD 128
#define EE 1600000
#define NEG_SLOPE 0.2f

// ---------------- scratch (device globals; no runtime allocation) ----------
__device__ float g_xl[NN * DD];   // source-transformed feats (this layer)
__device__ float g_xr[NN * DD];   // target-transformed feats (this layer)
__device__ float g_h[NN * DD];    // layer-0 output / layer-1 input (pre-relu)
__device__ float g_h2[NN * DD];   // layer-1 output / layer-2 input (pre-relu)
__device__ float g_e[EE];         // edge scores, then exp(scores - max)
__device__ float g_m[NN];         // per-dst segment max
__device__ float g_s[NN];         // per-dst segment sum of exp
__device__ int   g_src[EE];       // int32 edge sources
__device__ int   g_dst[EE];       // int32 edge dests
__device__ int   g_is64;          // 1 if edge_index buffer is int64

// select output accumulation buffer per layer
__device__ __forceinline__ float* out_ptr(int sel, float* p) {
    return (sel == 0) ? g_h : (sel == 1) ? g_h2 : p;
}

__device__ __forceinline__ void atomicMaxF(float* addr, float v) {
    if (v >= 0.0f) atomicMax((int*)addr, __float_as_int(v));
    else           atomicMin((unsigned int*)addr, __float_as_uint(v));
}

// ---------------- dtype detection + edge index conversion ------------------
// If the buffer is int64, every odd 32-bit word is a high half of a value
// < 2^31 and thus 0. Check 256 odd words.
__global__ void detect_kernel(const int* __restrict__ ei32) {
    int t = threadIdx.x;                 // 0..255
    int v = ei32[2 * t + 1];
    unsigned ok = __ballot_sync(0xffffffffu, v == 0);
    __shared__ int nz;
    if (t == 0) nz = 0;
    __syncthreads();
    if ((t & 31) == 0 && ok != 0xffffffffu) atomicAdd(&nz, 1);
    __syncthreads();
    if (t == 0) g_is64 = (nz == 0) ? 1 : 0;
}

__global__ void convert_kernel(const void* __restrict__ ei) {
    int i = blockIdx.x * blockDim.x + threadIdx.x;
    if (i >= 2 * EE) return;
    int v;
    if (g_is64) v = (int)((const long long*)ei)[i];
    else        v = ((const int*)ei)[i];
    if (i < EE) g_src[i] = v;
    else        g_dst[i - EE] = v;
}

// ---------------- GEMM: C[M,128] = act(A)[M,128] @ W[128,128] --------------
__global__ void __launch_bounds__(256) gemm_xlxr(
    const float* __restrict__ x0,
    const float* __restrict__ Wlp,
    const float* __restrict__ Wrp,
    int layer)
{
    const float* __restrict__ A = (layer == 0) ? x0 : (layer == 1 ? g_h : g_h2);
    const float* __restrict__ W = (blockIdx.y == 0) ? Wlp : Wrp;
    float* __restrict__ C = (blockIdx.y == 0) ? g_xl : g_xr;
    const bool doRelu = (layer > 0);

    __shared__ float As[32][132];  // [k][row], padded
    __shared__ float Bs[32][132];  // [k][col], padded

    const int tid = threadIdx.x;
    const int tx = tid & 15;        // output col group (8 cols)
    const int ty = tid >> 4;        // output row group (8 rows)
    const int rowBase = blockIdx.x * 128;

    float acc[8][8];
#pragma unroll
    for (int i = 0; i < 8; i++)
#pragma unroll
        for (int j = 0; j < 8; j++) acc[i][j] = 0.0f;

    const int lk = (tid & 7) * 4;   // k offset within chunk for A load
    const int lr = tid >> 3;        // row within pass for A load
    const int bc = (tid & 31) * 4;  // col for B load
    const int bk = tid >> 5;        // k row for B load

    for (int kc = 0; kc < 128; kc += 32) {
#pragma unroll
        for (int rr = 0; rr < 128; rr += 32) {
            int row = rowBase + lr + rr;
            float4 v = make_float4(0.f, 0.f, 0.f, 0.f);
            if (row < NN) v = *(const float4*)&A[row * 128 + kc + lk];
            if (doRelu) {
                v.x = fmaxf(v.x, 0.f); v.y = fmaxf(v.y, 0.f);
                v.z = fmaxf(v.z, 0.f); v.w = fmaxf(v.w, 0.f);
            }
            As[lk + 0][lr + rr] = v.x;
            As[lk + 1][lr + rr] = v.y;
            As[lk + 2][lr + rr] = v.z;
            As[lk + 3][lr + rr] = v.w;
        }
#pragma unroll
        for (int kk = 0; kk < 32; kk += 8) {
            float4 v = *(const float4*)&W[(kc + bk + kk) * 128 + bc];
            *(float4*)&Bs[bk + kk][bc] = v;
        }
        __syncthreads();

#pragma unroll
        for (int k = 0; k < 32; k++) {
            float4 a0 = *(float4*)&As[k][ty * 8];
            float4 a1 = *(float4*)&As[k][ty * 8 + 4];
            float4 b0 = *(float4*)&Bs[k][tx * 8];
            float4 b1 = *(float4*)&Bs[k][tx * 8 + 4];
            float av[8] = {a0.x, a0.y, a0.z, a0.w, a1.x, a1.y, a1.z, a1.w};
            float bv[8] = {b0.x, b0.y, b0.z, b0.w, b1.x, b1.y, b1.z, b1.w};
#pragma unroll
            for (int i = 0; i < 8; i++)
#pragma unroll
                for (int j = 0; j < 8; j++)
                    acc[i][j] = fmaf(av[i], bv[j], acc[i][j]);
        }
        __syncthreads();
    }

#pragma unroll
    for (int i = 0; i < 8; i++) {
        int row = rowBase + ty * 8 + i;
        if (row < NN) {
            float4 o0 = make_float4(acc[i][0], acc[i][1], acc[i][2], acc[i][3]);
            float4 o1 = make_float4(acc[i][4], acc[i][5], acc[i][6], acc[i][7]);
            *(float4*)&C[row * 128 + tx * 8] = o0;
            *(float4*)&C[row * 128 + tx * 8 + 4] = o1;
        }
    }
}

// ---------------- init: out = bias broadcast; m=-inf; s=0 ------------------
__global__ void init_kernel(const float* __restrict__ bptr, float* p, int sel) {
    int i = blockIdx.x * blockDim.x + threadIdx.x;
    float* out = out_ptr(sel, p);
    if (i < NN * DD) out[i] = bptr[i & 127];
    if (i < NN) { g_m[i] = __int_as_float(0xff800000); g_s[i] = 0.0f; }
}

// ---------------- per-edge score: e = att . leakyrelu(xl[src]+xr[dst]) ----
__global__ void __launch_bounds__(256) edge_score(const float* __restrict__ att)
{
    long long gt = (long long)blockIdx.x * blockDim.x + threadIdx.x;
    int e = (int)(gt >> 5);
    int lane = (int)(gt & 31);
    if (e >= EE) return;
    int s = g_src[e];
    int d = g_dst[e];
    float4 a = *(const float4*)&g_xl[(long long)s * 128 + lane * 4];
    float4 b = *(const float4*)&g_xr[(long long)d * 128 + lane * 4];
    float4 w = *(const float4*)&att[lane * 4];
    float ux = a.x + b.x; ux = (ux > 0.f) ? ux : NEG_SLOPE * ux;
    float uy = a.y + b.y; uy = (uy > 0.f) ? uy : NEG_SLOPE * uy;
    float uz = a.z + b.z; uz = (uz > 0.f) ? uz : NEG_SLOPE * uz;
    float uw = a.w + b.w; uw = (uw > 0.f) ? uw : NEG_SLOPE * uw;
    float p = ux * w.x + uy * w.y + uz * w.z + uw * w.w;
#pragma unroll
    for (int o = 16; o > 0; o >>= 1) p += __shfl_xor_sync(0xffffffffu, p, o);
    if (lane == 0) {
        g_e[e] = p;
        atomicMaxF(&g_m[d], p);
    }
}

// ---------------- per-edge exp + segment sum -------------------------------
__global__ void __launch_bounds__(256) edge_exp() {
    int e = blockIdx.x * blockDim.x + threadIdx.x;
    if (e >= EE) return;
    int d = g_dst[e];
    float ex = __expf(g_e[e] - g_m[d]);
    g_e[e] = ex;
    atomicAdd(&g_s[d], ex);
}

// ---------------- per-edge aggregation: out[dst] += alpha * xl[src] --------
__global__ void __launch_bounds__(256) edge_agg(float* p, int sel)
{
    long long gt = (long long)blockIdx.x * blockDim.x + threadIdx.x;
    int e = (int)(gt >> 5);
    int lane = (int)(gt & 31);
    if (e >= EE) return;
    float* out = out_ptr(sel, p);
    int s = g_src[e];
    int d = g_dst[e];
    float alpha = g_e[e] / (g_s[d] + 1e-16f);
    float4 v = *(const float4*)&g_xl[(long long)s * 128 + lane * 4];
    float* o = &out[(long long)d * 128 + lane * 4];
    atomicAdd(o + 0, alpha * v.x);
    atomicAdd(o + 1, alpha * v.y);
    atomicAdd(o + 2, alpha * v.z);
    atomicAdd(o + 3, alpha * v.w);
}

// ---------------- host ------------------------------------------------------
extern "C" void kernel_launch(void* const* d_in, const int* in_sizes, int n_in,
                              void* d_out, int out_size)
{
    const float* x      = (const float*)d_in[0];
    const float* Wl     = (const float*)d_in[1];   // [3,128,128]
    const float* Wr     = (const float*)d_in[2];   // [3,128,128]
    const float* att    = (const float*)d_in[3];   // [3,128]
    const float* b      = (const float*)d_in[4];   // [3,128]
    const void*  ei     = d_in[5];                 // [2,E] int32 or int64
    float* outp = (float*)d_out;

    detect_kernel<<<1, 256>>>((const int*)ei);
    convert_kernel<<<(2 * EE + 255) / 256, 256>>>(ei);

    dim3 gemmGrid((NN + 127) / 128, 2);
    int initBlocks  = (NN * DD + 255) / 256;
    long long warpThreads = (long long)EE * 32;
    int warpBlocks  = (int)((warpThreads + 255) / 256);
    int expBlocks   = (EE + 255) / 256;

    for (int layer = 0; layer < 3; layer++) {
        gemm_xlxr<<<gemmGrid, 256>>>(x, Wl + layer * DD * DD, Wr + layer * DD * DD, layer);
        init_kernel<<<initBlocks, 256>>>(b + layer * DD, outp, layer);
        edge_score<<<warpBlocks, 256>>>(att + layer * DD);
        edge_exp<<<expBlocks, 256>>>();
        edge_agg<<<warpBlocks, 256>>>(outp, layer);
    }
}

// round 3
// speedup vs baseline: 2.6687x; 2.6687x over previous
#include <cuda_runtime.h>
#include <math_constants.h>

#define NN 100000
#define DD 128
#define EE 1600000
#define NEG_SLOPE 0.2f
#define NB ((NN + 255) / 256)   // 391 scan blocks

// ---------------- scratch (device globals; no runtime allocation) ----------
__device__ float g_xl[NN * DD];   // source-transformed feats (this layer)
__device__ float g_xr[NN * DD];   // target-transformed feats (this layer)
__device__ float g_h[NN * DD];    // layer-0 output
__device__ float g_h2[NN * DD];   // layer-1 output
__device__ int   g_src[EE];
__device__ int   g_dst[EE];
__device__ int   g_deg[NN];       // in-degree histogram
__device__ int   g_off[NN];       // CSR offsets (start of each dst segment)
__device__ int   g_cur[NN];       // scatter cursors
__device__ int   g_psrc[EE];      // src ids permuted into dst-sorted order
__device__ int   g_bsum[NB];      // per-block bin sums
__device__ int   g_bbase[512];    // exclusive scan of block sums
__device__ int   g_is64;

__device__ __forceinline__ float* out_ptr(int sel, float* p) {
    return (sel == 0) ? g_h : (sel == 1) ? g_h2 : p;
}

// ---------------- dtype detection + edge index conversion ------------------
__global__ void detect_kernel(const int* __restrict__ ei32) {
    int t = threadIdx.x;
    int v = ei32[2 * t + 1];
    unsigned ok = __ballot_sync(0xffffffffu, v == 0);
    __shared__ int nz;
    if (t == 0) nz = 0;
    __syncthreads();
    if ((t & 31) == 0 && ok != 0xffffffffu) atomicAdd(&nz, 1);
    __syncthreads();
    if (t == 0) g_is64 = (nz == 0) ? 1 : 0;
}

// convert + zero the degree histogram
__global__ void convert_kernel(const void* __restrict__ ei) {
    int i = blockIdx.x * blockDim.x + threadIdx.x;
    if (i < NN) g_deg[i] = 0;
    if (i >= 2 * EE) return;
    int v;
    if (g_is64) v = (int)((const long long*)ei)[i];
    else        v = ((const int*)ei)[i];
    if (i < EE) g_src[i] = v;
    else        g_dst[i - EE] = v;
}

__global__ void hist_kernel() {
    int e = blockIdx.x * blockDim.x + threadIdx.x;
    if (e < EE) atomicAdd(&g_deg[g_dst[e]], 1);
}

// per-256-bin block sums
__global__ void blocksum_kernel() {
    int b = blockIdx.x * 256 + threadIdx.x;
    int d = (b < NN) ? g_deg[b] : 0;
#pragma unroll
    for (int o = 16; o > 0; o >>= 1) d += __shfl_xor_sync(0xffffffffu, d, o);
    __shared__ int ws[8];
    if ((threadIdx.x & 31) == 0) ws[threadIdx.x >> 5] = d;
    __syncthreads();
    if (threadIdx.x == 0) {
        int t = 0;
#pragma unroll
        for (int i = 0; i < 8; i++) t += ws[i];
        g_bsum[blockIdx.x] = t;
    }
}

// exclusive scan of the NB block sums (single block, 512 threads)
__global__ void scanbsum_kernel() {
    __shared__ int s[512];
    int t = threadIdx.x;
    int v = (t < NB) ? g_bsum[t] : 0;
    s[t] = v;
    __syncthreads();
    for (int o = 1; o < 512; o <<= 1) {
        int a = (t >= o) ? s[t - o] : 0;
        __syncthreads();
        s[t] += a;
        __syncthreads();
    }
    g_bbase[t] = s[t] - v;  // exclusive
}

// per-block exclusive scan of 256 bins + base -> offsets & cursors
__global__ void binscan_kernel() {
    __shared__ int s[256];
    int t = threadIdx.x;
    int b = blockIdx.x * 256 + t;
    int d = (b < NN) ? g_deg[b] : 0;
    s[t] = d;
    __syncthreads();
    for (int o = 1; o < 256; o <<= 1) {
        int a = (t >= o) ? s[t - o] : 0;
        __syncthreads();
        s[t] += a;
        __syncthreads();
    }
    if (b < NN) {
        int off = g_bbase[blockIdx.x] + s[t] - d;
        g_off[b] = off;
        g_cur[b] = off;
    }
}

__global__ void scatter_kernel() {
    int e = blockIdx.x * blockDim.x + threadIdx.x;
    if (e >= EE) return;
    int d = g_dst[e];
    int pos = atomicAdd(&g_cur[d], 1);
    g_psrc[pos] = g_src[e];
}

// ---------------- GEMM: C[M,128] = act(A)[M,128] @ W[128,128] --------------
__global__ void __launch_bounds__(256) gemm_xlxr(
    const float* __restrict__ x0,
    const float* __restrict__ Wlp,
    const float* __restrict__ Wrp,
    int layer)
{
    const float* __restrict__ A = (layer == 0) ? x0 : (layer == 1 ? g_h : g_h2);
    const float* __restrict__ W = (blockIdx.y == 0) ? Wlp : Wrp;
    float* __restrict__ C = (blockIdx.y == 0) ? g_xl : g_xr;
    const bool doRelu = (layer > 0);

    __shared__ float As[32][132];
    __shared__ float Bs[32][132];

    const int tid = threadIdx.x;
    const int tx = tid & 15;
    const int ty = tid >> 4;
    const int rowBase = blockIdx.x * 128;

    float acc[8][8];
#pragma unroll
    for (int i = 0; i < 8; i++)
#pragma unroll
        for (int j = 0; j < 8; j++) acc[i][j] = 0.0f;

    const int lk = (tid & 7) * 4;
    const int lr = tid >> 3;
    const int bc = (tid & 31) * 4;
    const int bk = tid >> 5;

    for (int kc = 0; kc < 128; kc += 32) {
#pragma unroll
        for (int rr = 0; rr < 128; rr += 32) {
            int row = rowBase + lr + rr;
            float4 v = make_float4(0.f, 0.f, 0.f, 0.f);
            if (row < NN) v = *(const float4*)&A[row * 128 + kc + lk];
            if (doRelu) {
                v.x = fmaxf(v.x, 0.f); v.y = fmaxf(v.y, 0.f);
                v.z = fmaxf(v.z, 0.f); v.w = fmaxf(v.w, 0.f);
            }
            As[lk + 0][lr + rr] = v.x;
            As[lk + 1][lr + rr] = v.y;
            As[lk + 2][lr + rr] = v.z;
            As[lk + 3][lr + rr] = v.w;
        }
#pragma unroll
        for (int kk = 0; kk < 32; kk += 8) {
            float4 v = *(const float4*)&W[(kc + bk + kk) * 128 + bc];
            *(float4*)&Bs[bk + kk][bc] = v;
        }
        __syncthreads();

#pragma unroll
        for (int k = 0; k < 32; k++) {
            float4 a0 = *(float4*)&As[k][ty * 8];
            float4 a1 = *(float4*)&As[k][ty * 8 + 4];
            float4 b0 = *(float4*)&Bs[k][tx * 8];
            float4 b1 = *(float4*)&Bs[k][tx * 8 + 4];
            float av[8] = {a0.x, a0.y, a0.z, a0.w, a1.x, a1.y, a1.z, a1.w};
            float bv[8] = {b0.x, b0.y, b0.z, b0.w, b1.x, b1.y, b1.z, b1.w};
#pragma unroll
            for (int i = 0; i < 8; i++)
#pragma unroll
                for (int j = 0; j < 8; j++)
                    acc[i][j] = fmaf(av[i], bv[j], acc[i][j]);
        }
        __syncthreads();
    }

#pragma unroll
    for (int i = 0; i < 8; i++) {
        int row = rowBase + ty * 8 + i;
        if (row < NN) {
            float4 o0 = make_float4(acc[i][0], acc[i][1], acc[i][2], acc[i][3]);
            float4 o1 = make_float4(acc[i][4], acc[i][5], acc[i][6], acc[i][7]);
            *(float4*)&C[row * 128 + tx * 8] = o0;
            *(float4*)&C[row * 128 + tx * 8 + 4] = o1;
        }
    }
}

// ---------------- fused node kernel: online softmax aggregation -----------
// one warp per dst node; no atomics anywhere
__global__ void __launch_bounds__(256) node_fused(
    const float* __restrict__ att,
    const float* __restrict__ bias,
    float* p, int sel)
{
    int warp = (blockIdx.x * blockDim.x + threadIdx.x) >> 5;
    int lane = threadIdx.x & 31;
    if (warp >= NN) return;
    const int n = warp;

    float4 xr4 = *(const float4*)&g_xr[(long long)n * 128 + lane * 4];
    float4 w4  = *(const float4*)&att[lane * 4];

    int beg = g_off[n];
    int end = beg + g_deg[n];

    float m = -CUDART_INF_F;
    float ssum = 0.0f;
    float4 acc = make_float4(0.f, 0.f, 0.f, 0.f);

    for (int i = beg; i < end; i++) {
        int s = g_psrc[i];
        float4 v = *(const float4*)&g_xl[(long long)s * 128 + lane * 4];
        float zx = v.x + xr4.x; zx = (zx > 0.f) ? zx : NEG_SLOPE * zx;
        float zy = v.y + xr4.y; zy = (zy > 0.f) ? zy : NEG_SLOPE * zy;
        float zz = v.z + xr4.z; zz = (zz > 0.f) ? zz : NEG_SLOPE * zz;
        float zw = v.w + xr4.w; zw = (zw > 0.f) ? zw : NEG_SLOPE * zw;
        float pe = zx * w4.x + zy * w4.y + zz * w4.z + zw * w4.w;
#pragma unroll
        for (int o = 16; o > 0; o >>= 1) pe += __shfl_xor_sync(0xffffffffu, pe, o);
        // online softmax update (all lanes hold identical pe, m, ssum)
        float mn = fmaxf(m, pe);
        float corr = __expf(m - mn);     // 0 on first edge (m=-inf), 1 if no new max
        float wgt  = __expf(pe - mn);
        ssum = ssum * corr + wgt;
        acc.x = acc.x * corr + wgt * v.x;
        acc.y = acc.y * corr + wgt * v.y;
        acc.z = acc.z * corr + wgt * v.z;
        acc.w = acc.w * corr + wgt * v.w;
        m = mn;
    }

    float inv = 1.0f / (ssum + 1e-16f);
    float4 b4 = *(const float4*)&bias[lane * 4];
    float4 o;
    o.x = acc.x * inv + b4.x;
    o.y = acc.y * inv + b4.y;
    o.z = acc.z * inv + b4.z;
    o.w = acc.w * inv + b4.w;
    float* out = out_ptr(sel, p);
    *(float4*)&out[(long long)n * 128 + lane * 4] = o;
}

// ---------------- host ------------------------------------------------------
extern "C" void kernel_launch(void* const* d_in, const int* in_sizes, int n_in,
                              void* d_out, int out_size)
{
    const float* x   = (const float*)d_in[0];
    const float* Wl  = (const float*)d_in[1];   // [3,128,128]
    const float* Wr  = (const float*)d_in[2];   // [3,128,128]
    const float* att = (const float*)d_in[3];   // [3,128]
    const float* b   = (const float*)d_in[4];   // [3,128]
    const void*  ei  = d_in[5];                 // [2,E] int32 or int64
    float* outp = (float*)d_out;

    // ---- CSR build (once per launch) ----
    detect_kernel<<<1, 256>>>((const int*)ei);
    convert_kernel<<<(2 * EE + 255) / 256, 256>>>(ei);
    hist_kernel<<<(EE + 255) / 256, 256>>>();
    blocksum_kernel<<<NB, 256>>>();
    scanbsum_kernel<<<1, 512>>>();
    binscan_kernel<<<NB, 256>>>();
    scatter_kernel<<<(EE + 255) / 256, 256>>>();

    dim3 gemmGrid((NN + 127) / 128, 2);
    int nodeBlocks = (NN * 32 + 255) / 256;

    for (int layer = 0; layer < 3; layer++) {
        gemm_xlxr<<<gemmGrid, 256>>>(x, Wl + layer * DD * DD, Wr + layer * DD * DD, layer);
        node_fused<<<nodeBlocks, 256>>>(att + layer * DD, b + layer * DD, outp, layer);
    }
}

// round 5
// speedup vs baseline: 3.2102x; 1.2029x over previous
#include <cuda_runtime.h>
#include <cuda_bf16.h>
#include <math_constants.h>
#include <cstdint>

#define NN 100000
#define NPAD 100096          // 782 * 128
#define DD 128
#define EE 1600000
#define NEG_SLOPE 0.2f
#define NB ((NN + 255) / 256)

// ---------------- scratch (device globals; no runtime allocation) ----------
__device__ float g_xl[NPAD * DD];           // GEMM-l output (fp32)
__device__ float g_xr[NPAD * DD];           // GEMM-r output (fp32)
__device__ __nv_bfloat16 g_Ah[NPAD * DD];   // split-hi node features (GEMM A input)
__device__ __nv_bfloat16 g_Al[NPAD * DD];   // split-lo node features
__device__ __nv_bfloat16 g_Bh[6][DD * DD];  // W^T [n][k] row-major, hi
__device__ __nv_bfloat16 g_Bl[6][DD * DD];  // ... lo
__device__ int   g_src[EE];
__device__ int   g_dst[EE];
__device__ int   g_deg[NN];
__device__ int   g_off[NN];
__device__ int   g_cur[NN];
__device__ int   g_psrc[EE];
__device__ int   g_bsum[NB];
__device__ int   g_bbase[512];
__device__ int   g_is64;

// ---------------- helpers ----------------------------------------------------
__device__ __forceinline__ uint32_t smem_u32(const void* p) {
    uint32_t a;
    asm("{ .reg .u64 t; cvta.to.shared.u64 t, %1; cvt.u32.u64 %0, t; }" : "=r"(a) : "l"(p));
    return a;
}
__device__ __forceinline__ void ldmatrix_x4(uint32_t& r0, uint32_t& r1,
                                            uint32_t& r2, uint32_t& r3, uint32_t addr) {
    asm volatile("ldmatrix.sync.aligned.m8n8.x4.shared.b16 {%0,%1,%2,%3}, [%4];"
        : "=r"(r0), "=r"(r1), "=r"(r2), "=r"(r3) : "r"(addr));
}
__device__ __forceinline__ void mma_bf16(float* c, const uint32_t* a, const uint32_t* b) {
    asm volatile("mma.sync.aligned.m16n8k16.row.col.f32.bf16.bf16.f32 "
        "{%0,%1,%2,%3}, {%4,%5,%6,%7}, {%8,%9}, {%0,%1,%2,%3};"
        : "+f"(c[0]), "+f"(c[1]), "+f"(c[2]), "+f"(c[3])
        : "r"(a[0]), "r"(a[1]), "r"(a[2]), "r"(a[3]), "r"(b[0]), "r"(b[1]));
}
__device__ __forceinline__ void split1(float v, __nv_bfloat16& hi, __nv_bfloat16& lo) {
    hi = __float2bfloat16(v);
    lo = __float2bfloat16(v - __bfloat162float(hi));
}

// ---------------- dtype detection + edge index conversion ------------------
__global__ void detect_kernel(const int* __restrict__ ei32) {
    int t = threadIdx.x;
    int v = ei32[2 * t + 1];
    unsigned ok = __ballot_sync(0xffffffffu, v == 0);
    __shared__ int nz;
    if (t == 0) nz = 0;
    __syncthreads();
    if ((t & 31) == 0 && ok != 0xffffffffu) atomicAdd(&nz, 1);
    __syncthreads();
    if (t == 0) g_is64 = (nz == 0) ? 1 : 0;
}

__global__ void convert_kernel(const void* __restrict__ ei) {
    int i = blockIdx.x * blockDim.x + threadIdx.x;
    if (i < NN) g_deg[i] = 0;
    if (i >= 2 * EE) return;
    int v;
    if (g_is64) v = (int)((const long long*)ei)[i];
    else        v = ((const int*)ei)[i];
    if (i < EE) g_src[i] = v;
    else        g_dst[i - EE] = v;
}

__global__ void hist_kernel() {
    int e = blockIdx.x * blockDim.x + threadIdx.x;
    if (e < EE) atomicAdd(&g_deg[g_dst[e]], 1);
}

__global__ void blocksum_kernel() {
    int b = blockIdx.x * 256 + threadIdx.x;
    int d = (b < NN) ? g_deg[b] : 0;
#pragma unroll
    for (int o = 16; o > 0; o >>= 1) d += __shfl_xor_sync(0xffffffffu, d, o);
    __shared__ int ws[8];
    if ((threadIdx.x & 31) == 0) ws[threadIdx.x >> 5] = d;
    __syncthreads();
    if (threadIdx.x == 0) {
        int t = 0;
#pragma unroll
        for (int i = 0; i < 8; i++) t += ws[i];
        g_bsum[blockIdx.x] = t;
    }
}

__global__ void scanbsum_kernel() {
    __shared__ int s[512];
    int t = threadIdx.x;
    int v = (t < NB) ? g_bsum[t] : 0;
    s[t] = v;
    __syncthreads();
    for (int o = 1; o < 512; o <<= 1) {
        int a = (t >= o) ? s[t - o] : 0;
        __syncthreads();
        s[t] += a;
        __syncthreads();
    }
    g_bbase[t] = s[t] - v;
}

__global__ void binscan_kernel() {
    __shared__ int s[256];
    int t = threadIdx.x;
    int b = blockIdx.x * 256 + t;
    int d = (b < NN) ? g_deg[b] : 0;
    s[t] = d;
    __syncthreads();
    for (int o = 1; o < 256; o <<= 1) {
        int a = (t >= o) ? s[t - o] : 0;
        __syncthreads();
        s[t] += a;
        __syncthreads();
    }
    if (b < NN) {
        int off = g_bbase[blockIdx.x] + s[t] - d;
        g_off[b] = off;
        g_cur[b] = off;
    }
}

__global__ void scatter_kernel() {
    int e = blockIdx.x * blockDim.x + threadIdx.x;
    if (e >= EE) return;
    int d = g_dst[e];
    int pos = atomicAdd(&g_cur[d], 1);
    g_psrc[pos] = g_src[e];
}

// ---------------- W conversion: transpose + split ---------------------------
// dest: [n][k] row-major bf16 (col-major from mma's perspective)
__global__ void conv_W(const float* __restrict__ Wl, const float* __restrict__ Wr) {
    int idx = blockIdx.x * 256 + threadIdx.x;   // 0..98303
    int m = idx >> 14;                          // matrix 0..5
    int r = idx & 16383;
    int k = r >> 7;
    int n = r & 127;
    int layer = m >> 1;
    const float* src = (m & 1) ? Wr : Wl;
    float v = src[layer * 16384 + k * 128 + n];
    __nv_bfloat16 hi, lo;
    split1(v, hi, lo);
    g_Bh[m][n * 128 + k] = hi;
    g_Bl[m][n * 128 + k] = lo;
}

// ---------------- x conversion (layer 0 A input) ---------------------------
__global__ void conv_x(const float* __restrict__ x) {
    int idx = blockIdx.x * blockDim.x + threadIdx.x;   // per float4
    if (idx >= NN * 32) return;
    float4 v = ((const float4*)x)[idx];
    __nv_bfloat16 hx, hy, hz, hw, lx, ly, lz, lw;
    split1(v.x, hx, lx); split1(v.y, hy, ly);
    split1(v.z, hz, lz); split1(v.w, hw, lw);
    __nv_bfloat162* ph = (__nv_bfloat162*)g_Ah + idx * 2;
    __nv_bfloat162* pl = (__nv_bfloat162*)g_Al + idx * 2;
    ph[0] = __nv_bfloat162(hx, hy); ph[1] = __nv_bfloat162(hz, hw);
    pl[0] = __nv_bfloat162(lx, ly); pl[1] = __nv_bfloat162(lz, lw);
}

// ---------------- tensor-core GEMM via mma.sync (split bf16, 3 terms) ------
// CTA tile 128x128, warp tile 64x32. Row stride in smem = 136 bf16 (272 B),
// conflict-free for ldmatrix (row-start bank shifts by 4 per row).
#define SROW 136
#define SA_H 0
#define SA_L 34816
#define SB_H 69632
#define SB_L 104448
#define GEMM_SMEM 139264

__global__ void __launch_bounds__(256, 1) gemm_mma(int layer) {
    extern __shared__ char smem[];
    const int tid = threadIdx.x;
    const int wid = tid >> 5;
    const int lane = tid & 31;
    const int rowBase = blockIdx.x * 128;
    const int mat = layer * 2 + blockIdx.y;

    // load A (hi/lo) rows rowBase..+127 and B (hi/lo) into padded smem
    {
        const uint4* aH = (const uint4*)g_Ah;
        const uint4* aL = (const uint4*)g_Al;
        const uint4* bH = (const uint4*)g_Bh[mat];
        const uint4* bL = (const uint4*)g_Bl[mat];
        for (int idx = tid; idx < 2048; idx += 256) {
            int r = idx >> 4, j = idx & 15;
            uint32_t doff = r * 272 + j * 16;
            *(uint4*)(smem + SA_H + doff) = aH[(rowBase + r) * 16 + j];
            *(uint4*)(smem + SA_L + doff) = aL[(rowBase + r) * 16 + j];
            *(uint4*)(smem + SB_H + doff) = bH[idx];
            *(uint4*)(smem + SB_L + doff) = bL[idx];
        }
    }
    __syncthreads();

    const int m0 = (wid >> 2) * 64;     // 0 or 64
    const int n0 = (wid & 3) * 32;      // 0,32,64,96

    float acc[4][4][4];
#pragma unroll
    for (int i = 0; i < 4; i++)
#pragma unroll
        for (int j = 0; j < 4; j++)
#pragma unroll
            for (int q = 0; q < 4; q++) acc[i][j][q] = 0.0f;

    const uint32_t sbase = smem_u32(smem);
    // A fragment address: row = m0 + mi*16 + (lane&15), col = k0 + 8*(lane>>4)
    const uint32_t a_row = m0 + (lane & 15);
    const uint32_t a_coff = ((lane >> 4) << 3) * 2;
    // B fragment address (x4 covers two n8 tiles):
    const int quad = lane >> 3;
    const uint32_t b_row = n0 + ((quad >> 1) << 3) + (lane & 7);
    const uint32_t b_coff = ((quad & 1) << 3) * 2;

#pragma unroll
    for (int ks = 0; ks < 8; ks++) {
        const uint32_t k0b = ks * 32;   // k0 * 2 bytes
        uint32_t aHf[4][4], aLf[4][4];
#pragma unroll
        for (int mi = 0; mi < 4; mi++) {
            uint32_t ad = sbase + SA_H + (a_row + mi * 16) * 272 + k0b + a_coff;
            ldmatrix_x4(aHf[mi][0], aHf[mi][1], aHf[mi][2], aHf[mi][3], ad);
            ldmatrix_x4(aLf[mi][0], aLf[mi][1], aLf[mi][2], aLf[mi][3], ad + (SA_L - SA_H));
        }
        uint32_t bHf[4][2], bLf[4][2];
#pragma unroll
        for (int p = 0; p < 2; p++) {
            uint32_t bd = sbase + SB_H + (b_row + p * 16) * 272 + k0b + b_coff;
            uint32_t r0, r1, r2, r3;
            ldmatrix_x4(r0, r1, r2, r3, bd);
            bHf[p * 2][0] = r0; bHf[p * 2][1] = r1;
            bHf[p * 2 + 1][0] = r2; bHf[p * 2 + 1][1] = r3;
            ldmatrix_x4(r0, r1, r2, r3, bd + (SB_L - SB_H));
            bLf[p * 2][0] = r0; bLf[p * 2][1] = r1;
            bLf[p * 2 + 1][0] = r2; bLf[p * 2 + 1][1] = r3;
        }
#pragma unroll
        for (int mi = 0; mi < 4; mi++)
#pragma unroll
            for (int ni = 0; ni < 4; ni++) {
                mma_bf16(acc[mi][ni], aHf[mi], bHf[ni]);
                mma_bf16(acc[mi][ni], aLf[mi], bHf[ni]);
                mma_bf16(acc[mi][ni], aHf[mi], bLf[ni]);
            }
    }

    // epilogue: direct float2 stores
    float* __restrict__ C = (blockIdx.y == 0) ? g_xl : g_xr;
#pragma unroll
    for (int mi = 0; mi < 4; mi++) {
#pragma unroll
        for (int ni = 0; ni < 4; ni++) {
            int row0 = rowBase + m0 + mi * 16 + (lane >> 2);
            int col = n0 + ni * 8 + (lane & 3) * 2;
            if (row0 < NN)
                *(float2*)&C[row0 * 128 + col] = make_float2(acc[mi][ni][0], acc[mi][ni][1]);
            int row1 = row0 + 8;
            if (row1 < NN)
                *(float2*)&C[row1 * 128 + col] = make_float2(acc[mi][ni][2], acc[mi][ni][3]);
        }
    }
}

// ---------------- fused node kernel: online softmax aggregation -----------
__global__ void __launch_bounds__(256) node_fused(
    const float* __restrict__ att,
    const float* __restrict__ bias,
    float* __restrict__ outp, int sel)
{
    int warp = (blockIdx.x * blockDim.x + threadIdx.x) >> 5;
    int lane = threadIdx.x & 31;
    if (warp >= NN) return;
    const int n = warp;

    float4 xr4 = *(const float4*)&g_xr[(long long)n * 128 + lane * 4];
    float4 w4  = *(const float4*)&att[lane * 4];

    int beg = g_off[n];
    int end = beg + g_deg[n];

    float m = -CUDART_INF_F;
    float ssum = 0.0f;
    float4 acc = make_float4(0.f, 0.f, 0.f, 0.f);

    for (int i = beg; i < end; i++) {
        int s = g_psrc[i];
        float4 v = *(const float4*)&g_xl[(long long)s * 128 + lane * 4];
        float zx = v.x + xr4.x; zx = (zx > 0.f) ? zx : NEG_SLOPE * zx;
        float zy = v.y + xr4.y; zy = (zy > 0.f) ? zy : NEG_SLOPE * zy;
        float zz = v.z + xr4.z; zz = (zz > 0.f) ? zz : NEG_SLOPE * zz;
        float zw = v.w + xr4.w; zw = (zw > 0.f) ? zw : NEG_SLOPE * zw;
        float pe = zx * w4.x + zy * w4.y + zz * w4.z + zw * w4.w;
#pragma unroll
        for (int o = 16; o > 0; o >>= 1) pe += __shfl_xor_sync(0xffffffffu, pe, o);
        float mn = fmaxf(m, pe);
        float corr = __expf(m - mn);
        float wgt  = __expf(pe - mn);
        ssum = ssum * corr + wgt;
        acc.x = acc.x * corr + wgt * v.x;
        acc.y = acc.y * corr + wgt * v.y;
        acc.z = acc.z * corr + wgt * v.z;
        acc.w = acc.w * corr + wgt * v.w;
        m = mn;
    }

    float inv = 1.0f / (ssum + 1e-16f);
    float4 b4 = *(const float4*)&bias[lane * 4];
    float4 o;
    o.x = acc.x * inv + b4.x;
    o.y = acc.y * inv + b4.y;
    o.z = acc.z * inv + b4.z;
    o.w = acc.w * inv + b4.w;

    if (sel == 2) {
        *(float4*)&outp[(long long)n * 128 + lane * 4] = o;
    } else {
        o.x = fmaxf(o.x, 0.f); o.y = fmaxf(o.y, 0.f);
        o.z = fmaxf(o.z, 0.f); o.w = fmaxf(o.w, 0.f);
        __nv_bfloat16 hx, hy, hz, hw, lx, ly, lz, lw;
        split1(o.x, hx, lx); split1(o.y, hy, ly);
        split1(o.z, hz, lz); split1(o.w, hw, lw);
        __nv_bfloat162* ph = (__nv_bfloat162*)&g_Ah[n * 128 + lane * 4];
        __nv_bfloat162* pl = (__nv_bfloat162*)&g_Al[n * 128 + lane * 4];
        ph[0] = __nv_bfloat162(hx, hy); ph[1] = __nv_bfloat162(hz, hw);
        pl[0] = __nv_bfloat162(lx, ly); pl[1] = __nv_bfloat162(lz, lw);
    }
}

// ---------------- host ------------------------------------------------------
extern "C" void kernel_launch(void* const* d_in, const int* in_sizes, int n_in,
                              void* d_out, int out_size)
{
    const float* x   = (const float*)d_in[0];
    const float* Wl  = (const float*)d_in[1];   // [3,128,128]
    const float* Wr  = (const float*)d_in[2];   // [3,128,128]
    const float* att = (const float*)d_in[3];   // [3,128]
    const float* b   = (const float*)d_in[4];   // [3,128]
    const void*  ei  = d_in[5];                 // [2,E] int32 or int64
    float* outp = (float*)d_out;

    static int smem_set = 0;
    if (!smem_set) {
        cudaFuncSetAttribute(gemm_mma, cudaFuncAttributeMaxDynamicSharedMemorySize, GEMM_SMEM);
        smem_set = 1;
    }

    // ---- CSR build + weight/input split (once per launch) ----
    detect_kernel<<<1, 256>>>((const int*)ei);
    convert_kernel<<<(2 * EE + 255) / 256, 256>>>(ei);
    hist_kernel<<<(EE + 255) / 256, 256>>>();
    blocksum_kernel<<<NB, 256>>>();
    scanbsum_kernel<<<1, 512>>>();
    binscan_kernel<<<NB, 256>>>();
    scatter_kernel<<<(EE + 255) / 256, 256>>>();
    conv_W<<<384, 256>>>(Wl, Wr);
    conv_x<<<(NN * 32 + 255) / 256, 256>>>(x);

    dim3 gemmGrid(NPAD / 128, 2);
    int nodeBlocks = (NN * 32 + 255) / 256;

    for (int layer = 0; layer < 3; layer++) {
        gemm_mma<<<gemmGrid, 256, GEMM_SMEM>>>(layer);
        node_fused<<<nodeBlocks, 256>>>(att + layer * DD, b + layer * DD, outp, layer);
    }
}

// round 6
// speedup vs baseline: 3.9798x; 1.2397x over previous
#include <cuda_runtime.h>
#include <cuda_bf16.h>
#include <math_constants.h>
#include <cstdint>

#define NN 100000
#define NPAD 100096          // 782 * 128
#define DD 128
#define EE 1600000
#define NEG_SLOPE 0.2f
#define NB ((NN + 255) / 256)

// ---------------- scratch (device globals; no runtime allocation) ----------
__device__ float g_xl[NPAD * DD];           // GEMM-l output (fp32)
__device__ float g_xr[NPAD * DD];           // GEMM-r output (fp32)
__device__ __nv_bfloat16 g_Ah[NPAD * DD];   // split-hi node features (GEMM A input)
__device__ __nv_bfloat16 g_Al[NPAD * DD];   // split-lo node features
__device__ __nv_bfloat16 g_Bh[6][DD * DD];  // W^T [n][k] row-major, hi
__device__ __nv_bfloat16 g_Bl[6][DD * DD];  // ... lo
__device__ int   g_src[EE];
__device__ int   g_dst[EE];
__device__ int   g_deg[NN];
__device__ int   g_off[NN];
__device__ int   g_cur[NN];
__device__ int   g_psrc[EE];
__device__ int   g_bsum[NB];
__device__ int   g_bbase[512];
__device__ int   g_is64;

// ---------------- helpers ----------------------------------------------------
__device__ __forceinline__ uint32_t smem_u32(const void* p) {
    uint32_t a;
    asm("{ .reg .u64 t; cvta.to.shared.u64 t, %1; cvt.u32.u64 %0, t; }" : "=r"(a) : "l"(p));
    return a;
}
__device__ __forceinline__ void ldmatrix_x4(uint32_t& r0, uint32_t& r1,
                                            uint32_t& r2, uint32_t& r3, uint32_t addr) {
    asm volatile("ldmatrix.sync.aligned.m8n8.x4.shared.b16 {%0,%1,%2,%3}, [%4];"
        : "=r"(r0), "=r"(r1), "=r"(r2), "=r"(r3) : "r"(addr));
}
__device__ __forceinline__ void mma_bf16(float* c, const uint32_t* a, const uint32_t* b) {
    asm volatile("mma.sync.aligned.m16n8k16.row.col.f32.bf16.bf16.f32 "
        "{%0,%1,%2,%3}, {%4,%5,%6,%7}, {%8,%9}, {%0,%1,%2,%3};"
        : "+f"(c[0]), "+f"(c[1]), "+f"(c[2]), "+f"(c[3])
        : "r"(a[0]), "r"(a[1]), "r"(a[2]), "r"(a[3]), "r"(b[0]), "r"(b[1]));
}
__device__ __forceinline__ void split1(float v, __nv_bfloat16& hi, __nv_bfloat16& lo) {
    hi = __float2bfloat16(v);
    lo = __float2bfloat16(v - __bfloat162float(hi));
}

// ---------------- dtype detection + edge index conversion ------------------
__global__ void detect_kernel(const int* __restrict__ ei32) {
    int t = threadIdx.x;
    int v = ei32[2 * t + 1];
    unsigned ok = __ballot_sync(0xffffffffu, v == 0);
    __shared__ int nz;
    if (t == 0) nz = 0;
    __syncthreads();
    if ((t & 31) == 0 && ok != 0xffffffffu) atomicAdd(&nz, 1);
    __syncthreads();
    if (t == 0) g_is64 = (nz == 0) ? 1 : 0;
}

__global__ void convert_kernel(const void* __restrict__ ei) {
    int i = blockIdx.x * blockDim.x + threadIdx.x;
    if (i < NN) g_deg[i] = 0;
    if (i >= 2 * EE) return;
    int v;
    if (g_is64) v = (int)((const long long*)ei)[i];
    else        v = ((const int*)ei)[i];
    if (i < EE) g_src[i] = v;
    else        g_dst[i - EE] = v;
}

__global__ void hist_kernel() {
    int e = blockIdx.x * blockDim.x + threadIdx.x;
    if (e < EE) atomicAdd(&g_deg[g_dst[e]], 1);
}

__global__ void blocksum_kernel() {
    int b = blockIdx.x * 256 + threadIdx.x;
    int d = (b < NN) ? g_deg[b] : 0;
#pragma unroll
    for (int o = 16; o > 0; o >>= 1) d += __shfl_xor_sync(0xffffffffu, d, o);
    __shared__ int ws[8];
    if ((threadIdx.x & 31) == 0) ws[threadIdx.x >> 5] = d;
    __syncthreads();
    if (threadIdx.x == 0) {
        int t = 0;
#pragma unroll
        for (int i = 0; i < 8; i++) t += ws[i];
        g_bsum[blockIdx.x] = t;
    }
}

__global__ void scanbsum_kernel() {
    __shared__ int s[512];
    int t = threadIdx.x;
    int v = (t < NB) ? g_bsum[t] : 0;
    s[t] = v;
    __syncthreads();
    for (int o = 1; o < 512; o <<= 1) {
        int a = (t >= o) ? s[t - o] : 0;
        __syncthreads();
        s[t] += a;
        __syncthreads();
    }
    g_bbase[t] = s[t] - v;
}

__global__ void binscan_kernel() {
    __shared__ int s[256];
    int t = threadIdx.x;
    int b = blockIdx.x * 256 + t;
    int d = (b < NN) ? g_deg[b] : 0;
    s[t] = d;
    __syncthreads();
    for (int o = 1; o < 256; o <<= 1) {
        int a = (t >= o) ? s[t - o] : 0;
        __syncthreads();
        s[t] += a;
        __syncthreads();
    }
    if (b < NN) {
        int off = g_bbase[blockIdx.x] + s[t] - d;
        g_off[b] = off;
        g_cur[b] = off;
    }
}

__global__ void scatter_kernel() {
    int e = blockIdx.x * blockDim.x + threadIdx.x;
    if (e >= EE) return;
    int d = g_dst[e];
    int pos = atomicAdd(&g_cur[d], 1);
    g_psrc[pos] = g_src[e];
}

// ---------------- W conversion: transpose + split ---------------------------
__global__ void conv_W(const float* __restrict__ Wl, const float* __restrict__ Wr) {
    int idx = blockIdx.x * 256 + threadIdx.x;   // 0..98303
    int m = idx >> 14;
    int r = idx & 16383;
    int k = r >> 7;
    int n = r & 127;
    int layer = m >> 1;
    const float* src = (m & 1) ? Wr : Wl;
    float v = src[layer * 16384 + k * 128 + n];
    __nv_bfloat16 hi, lo;
    split1(v, hi, lo);
    g_Bh[m][n * 128 + k] = hi;
    g_Bl[m][n * 128 + k] = lo;
}

// ---------------- x conversion (layer 0 A input) ---------------------------
__global__ void conv_x(const float* __restrict__ x) {
    int idx = blockIdx.x * blockDim.x + threadIdx.x;   // per float4
    if (idx >= NN * 32) return;
    float4 v = ((const float4*)x)[idx];
    __nv_bfloat16 hx, hy, hz, hw, lx, ly, lz, lw;
    split1(v.x, hx, lx); split1(v.y, hy, ly);
    split1(v.z, hz, lz); split1(v.w, hw, lw);
    __nv_bfloat162* ph = (__nv_bfloat162*)g_Ah + idx * 2;
    __nv_bfloat162* pl = (__nv_bfloat162*)g_Al + idx * 2;
    ph[0] = __nv_bfloat162(hx, hy); ph[1] = __nv_bfloat162(hz, hw);
    pl[0] = __nv_bfloat162(lx, ly); pl[1] = __nv_bfloat162(lz, lw);
}

// ---------------- tensor-core GEMM via mma.sync (split bf16, 3 terms) ------
// CTA tile 128x128, warp tile 64x32, K chunked 2x64 so smem=73.7KB -> 2 CTA/SM.
// Row stride 144 B (36 words, ≡4 mod 32) keeps ldmatrix conflict-free.
#define SROWB 144
#define SA_H 0
#define SA_L 18432
#define SB_H 36864
#define SB_L 55296
#define GEMM_SMEM 73728

__global__ void __launch_bounds__(256, 2) gemm_mma(int layer) {
    extern __shared__ char smem[];
    const int tid = threadIdx.x;
    const int wid = tid >> 5;
    const int lane = tid & 31;
    const int rowBase = blockIdx.x * 128;
    const int mat = layer * 2 + blockIdx.y;

    const int m0 = (wid >> 2) * 64;     // 0 or 64
    const int n0 = (wid & 3) * 32;      // 0,32,64,96

    float acc[4][4][4];
#pragma unroll
    for (int i = 0; i < 4; i++)
#pragma unroll
        for (int j = 0; j < 4; j++)
#pragma unroll
            for (int q = 0; q < 4; q++) acc[i][j][q] = 0.0f;

    const uint32_t sbase = smem_u32(smem);
    const uint32_t a_row = m0 + (lane & 15);
    const uint32_t a_coff = ((lane >> 4) << 3) * 2;
    const int quad = lane >> 3;
    const uint32_t b_row = n0 + ((quad >> 1) << 3) + (lane & 7);
    const uint32_t b_coff = ((quad & 1) << 3) * 2;

    const uint4* aHg = (const uint4*)g_Ah;
    const uint4* aLg = (const uint4*)g_Al;
    const uint4* bHg = (const uint4*)g_Bh[mat];
    const uint4* bLg = (const uint4*)g_Bl[mat];

#pragma unroll
    for (int kc = 0; kc < 2; kc++) {
        if (kc) __syncthreads();   // protect smem from prior compute
        // load chunk: 1024 uint4 per buffer
        for (int idx = tid; idx < 1024; idx += 256) {
            int r = idx >> 3, j = idx & 7;
            uint32_t doff = r * SROWB + j * 16;
            int ga = (rowBase + r) * 16 + kc * 8 + j;
            int gb = r * 16 + kc * 8 + j;
            *(uint4*)(smem + SA_H + doff) = aHg[ga];
            *(uint4*)(smem + SA_L + doff) = aLg[ga];
            *(uint4*)(smem + SB_H + doff) = bHg[gb];
            *(uint4*)(smem + SB_L + doff) = bLg[gb];
        }
        __syncthreads();

#pragma unroll
        for (int ks = 0; ks < 4; ks++) {
            const uint32_t k0b = ks * 32;
            uint32_t bHf[4][2], bLf[4][2];
#pragma unroll
            for (int p = 0; p < 2; p++) {
                uint32_t bd = sbase + SB_H + (b_row + p * 16) * SROWB + k0b + b_coff;
                uint32_t r0, r1, r2, r3;
                ldmatrix_x4(r0, r1, r2, r3, bd);
                bHf[p * 2][0] = r0; bHf[p * 2][1] = r1;
                bHf[p * 2 + 1][0] = r2; bHf[p * 2 + 1][1] = r3;
                ldmatrix_x4(r0, r1, r2, r3, bd + (SB_L - SB_H));
                bLf[p * 2][0] = r0; bLf[p * 2][1] = r1;
                bLf[p * 2 + 1][0] = r2; bLf[p * 2 + 1][1] = r3;
            }
#pragma unroll
            for (int mi = 0; mi < 4; mi++) {
                uint32_t aHf[4], aLf[4];
                uint32_t ad = sbase + SA_H + (a_row + mi * 16) * SROWB + k0b + a_coff;
                ldmatrix_x4(aHf[0], aHf[1], aHf[2], aHf[3], ad);
                ldmatrix_x4(aLf[0], aLf[1], aLf[2], aLf[3], ad + (SA_L - SA_H));
#pragma unroll
                for (int ni = 0; ni < 4; ni++) {
                    mma_bf16(acc[mi][ni], aHf, bHf[ni]);
                    mma_bf16(acc[mi][ni], aLf, bHf[ni]);
                    mma_bf16(acc[mi][ni], aHf, bLf[ni]);
                }
            }
        }
    }

    // epilogue: direct float2 stores
    float* __restrict__ C = (blockIdx.y == 0) ? g_xl : g_xr;
#pragma unroll
    for (int mi = 0; mi < 4; mi++) {
#pragma unroll
        for (int ni = 0; ni < 4; ni++) {
            int row0 = rowBase + m0 + mi * 16 + (lane >> 2);
            int col = n0 + ni * 8 + (lane & 3) * 2;
            if (row0 < NN)
                *(float2*)&C[row0 * 128 + col] = make_float2(acc[mi][ni][0], acc[mi][ni][1]);
            int row1 = row0 + 8;
            if (row1 < NN)
                *(float2*)&C[row1 * 128 + col] = make_float2(acc[mi][ni][2], acc[mi][ni][3]);
        }
    }
}

// ---------------- fused node kernel: online softmax aggregation -----------
__global__ void __launch_bounds__(256) node_fused(
    const float* __restrict__ att,
    const float* __restrict__ bias,
    float* __restrict__ outp, int sel)
{
    int warp = (blockIdx.x * blockDim.x + threadIdx.x) >> 5;
    int lane = threadIdx.x & 31;
    if (warp >= NN) return;
    const int n = warp;

    float4 xr4 = *(const float4*)&g_xr[(long long)n * 128 + lane * 4];
    float4 w4  = *(const float4*)&att[lane * 4];

    int beg = g_off[n];
    int end = beg + g_deg[n];

    float m = -CUDART_INF_F;
    float ssum = 0.0f;
    float4 acc = make_float4(0.f, 0.f, 0.f, 0.f);

    int i = beg;
    for (; i + 1 < end; i += 2) {
        int s0 = g_psrc[i];
        int s1 = g_psrc[i + 1];
        float4 v0 = *(const float4*)&g_xl[(long long)s0 * 128 + lane * 4];
        float4 v1 = *(const float4*)&g_xl[(long long)s1 * 128 + lane * 4];
        float z0x = v0.x + xr4.x; z0x = (z0x > 0.f) ? z0x : NEG_SLOPE * z0x;
        float z0y = v0.y + xr4.y; z0y = (z0y > 0.f) ? z0y : NEG_SLOPE * z0y;
        float z0z = v0.z + xr4.z; z0z = (z0z > 0.f) ? z0z : NEG_SLOPE * z0z;
        float z0w = v0.w + xr4.w; z0w = (z0w > 0.f) ? z0w : NEG_SLOPE * z0w;
        float z1x = v1.x + xr4.x; z1x = (z1x > 0.f) ? z1x : NEG_SLOPE * z1x;
        float z1y = v1.y + xr4.y; z1y = (z1y > 0.f) ? z1y : NEG_SLOPE * z1y;
        float z1z = v1.z + xr4.z; z1z = (z1z > 0.f) ? z1z : NEG_SLOPE * z1z;
        float z1w = v1.w + xr4.w; z1w = (z1w > 0.f) ? z1w : NEG_SLOPE * z1w;
        float p0 = z0x * w4.x + z0y * w4.y + z0z * w4.z + z0w * w4.w;
        float p1 = z1x * w4.x + z1y * w4.y + z1z * w4.z + z1w * w4.w;
#pragma unroll
        for (int o = 16; o > 0; o >>= 1) {
            p0 += __shfl_xor_sync(0xffffffffu, p0, o);
            p1 += __shfl_xor_sync(0xffffffffu, p1, o);
        }
        // edge 0
        float mn = fmaxf(m, p0);
        float corr = __expf(m - mn);
        float wgt  = __expf(p0 - mn);
        ssum = ssum * corr + wgt;
        acc.x = acc.x * corr + wgt * v0.x;
        acc.y = acc.y * corr + wgt * v0.y;
        acc.z = acc.z * corr + wgt * v0.z;
        acc.w = acc.w * corr + wgt * v0.w;
        m = mn;
        // edge 1
        mn = fmaxf(m, p1);
        corr = __expf(m - mn);
        wgt  = __expf(p1 - mn);
        ssum = ssum * corr + wgt;
        acc.x = acc.x * corr + wgt * v1.x;
        acc.y = acc.y * corr + wgt * v1.y;
        acc.z = acc.z * corr + wgt * v1.z;
        acc.w = acc.w * corr + wgt * v1.w;
        m = mn;
    }
    if (i < end) {
        int s = g_psrc[i];
        float4 v = *(const float4*)&g_xl[(long long)s * 128 + lane * 4];
        float zx = v.x + xr4.x; zx = (zx > 0.f) ? zx : NEG_SLOPE * zx;
        float zy = v.y + xr4.y; zy = (zy > 0.f) ? zy : NEG_SLOPE * zy;
        float zz = v.z + xr4.z; zz = (zz > 0.f) ? zz : NEG_SLOPE * zz;
        float zw = v.w + xr4.w; zw = (zw > 0.f) ? zw : NEG_SLOPE * zw;
        float pe = zx * w4.x + zy * w4.y + zz * w4.z + zw * w4.w;
#pragma unroll
        for (int o = 16; o > 0; o >>= 1) pe += __shfl_xor_sync(0xffffffffu, pe, o);
        float mn = fmaxf(m, pe);
        float corr = __expf(m - mn);
        float wgt  = __expf(pe - mn);
        ssum = ssum * corr + wgt;
        acc.x = acc.x * corr + wgt * v.x;
        acc.y = acc.y * corr + wgt * v.y;
        acc.z = acc.z * corr + wgt * v.z;
        acc.w = acc.w * corr + wgt * v.w;
        m = mn;
    }

    float inv = 1.0f / (ssum + 1e-16f);
    float4 b4 = *(const float4*)&bias[lane * 4];
    float4 o;
    o.x = acc.x * inv + b4.x;
    o.y = acc.y * inv + b4.y;
    o.z = acc.z * inv + b4.z;
    o.w = acc.w * inv + b4.w;

    if (sel == 2) {
        *(float4*)&outp[(long long)n * 128 + lane * 4] = o;
    } else {
        o.x = fmaxf(o.x, 0.f); o.y = fmaxf(o.y, 0.f);
        o.z = fmaxf(o.z, 0.f); o.w = fmaxf(o.w, 0.f);
        __nv_bfloat16 hx, hy, hz, hw, lx, ly, lz, lw;
        split1(o.x, hx, lx); split1(o.y, hy, ly);
        split1(o.z, hz, lz); split1(o.w, hw, lw);
        __nv_bfloat162* ph = (__nv_bfloat162*)&g_Ah[n * 128 + lane * 4];
        __nv_bfloat162* pl = (__nv_bfloat162*)&g_Al[n * 128 + lane * 4];
        ph[0] = __nv_bfloat162(hx, hy); ph[1] = __nv_bfloat162(hz, hw);
        pl[0] = __nv_bfloat162(lx, ly); pl[1] = __nv_bfloat162(lz, lw);
    }
}

// ---------------- host ------------------------------------------------------
extern "C" void kernel_launch(void* const* d_in, const int* in_sizes, int n_in,
                              void* d_out, int out_size)
{
    const float* x   = (const float*)d_in[0];
    const float* Wl  = (const float*)d_in[1];   // [3,128,128]
    const float* Wr  = (const float*)d_in[2];   // [3,128,128]
    const float* att = (const float*)d_in[3];   // [3,128]
    const float* b   = (const float*)d_in[4];   // [3,128]
    const void*  ei  = d_in[5];                 // [2,E] int32 or int64
    float* outp = (float*)d_out;

    cudaFuncSetAttribute(gemm_mma, cudaFuncAttributeMaxDynamicSharedMemorySize, GEMM_SMEM);

    dim3 gemmGrid(NPAD / 128, 2);
    int nodeBlocks = (NN * 32 + 255) / 256;

    // Launch order puts gemm_mma(layer 0) at launch index 5 so ncu -s 5 -c 1
    // captures the hot GEMM instead of CSR trivia.
    conv_W<<<384, 256>>>(Wl, Wr);                          // 0
    conv_x<<<(NN * 32 + 255) / 256, 256>>>(x);             // 1
    detect_kernel<<<1, 256>>>((const int*)ei);             // 2
    convert_kernel<<<(2 * EE + 255) / 256, 256>>>(ei);     // 3
    hist_kernel<<<(EE + 255) / 256, 256>>>();              // 4
    gemm_mma<<<gemmGrid, 256, GEMM_SMEM>>>(0);             // 5  <- profiled
    blocksum_kernel<<<NB, 256>>>();                        // 6
    scanbsum_kernel<<<1, 512>>>();                         // 7
    binscan_kernel<<<NB, 256>>>();                         // 8
    scatter_kernel<<<(EE + 255) / 256, 256>>>();           // 9
    node_fused<<<nodeBlocks, 256>>>(att, b, outp, 0);      // 10

    for (int layer = 1; layer < 3; layer++) {
        gemm_mma<<<gemmGrid, 256, GEMM_SMEM>>>(layer);
        node_fused<<<nodeBlocks, 256>>>(att + layer * DD, b + layer * DD, outp, layer);
    }
}

// round 7
// speedup vs baseline: 4.4110x; 1.1083x over previous
#include <cuda_runtime.h>
#include <cuda_bf16.h>
#include <math_constants.h>
#include <cstdint>

#define NN 100000
#define NPAD 100096          // 782 * 128
#define DD 128
#define EE 1600000
#define NEG_SLOPE 0.2f
#define NB ((NN + 255) / 256)

// ---------------- scratch (device globals; no runtime allocation) ----------
__device__ float g_xl[NPAD * DD];
__device__ float g_xr[NPAD * DD];
__device__ __nv_bfloat16 g_Ah[NPAD * DD];
__device__ __nv_bfloat16 g_Al[NPAD * DD];
__device__ __nv_bfloat16 g_Bh[6][DD * DD];  // W^T [n][k] row-major, hi
__device__ __nv_bfloat16 g_Bl[6][DD * DD];  // ... lo
__device__ int   g_src[EE];
__device__ int   g_dst[EE];
__device__ int   g_deg[NN];
__device__ int   g_off[NN];
__device__ int   g_cur[NN];
__device__ int   g_psrc[EE];
__device__ int   g_bsum[NB];
__device__ int   g_bbase[512];
__device__ int   g_is64;

// ---------------- helpers ----------------------------------------------------
__device__ __forceinline__ uint32_t smem_u32(const void* p) {
    uint32_t a;
    asm("{ .reg .u64 t; cvta.to.shared.u64 t, %1; cvt.u32.u64 %0, t; }" : "=r"(a) : "l"(p));
    return a;
}
__device__ __forceinline__ void ldmatrix_x4(uint32_t& r0, uint32_t& r1,
                                            uint32_t& r2, uint32_t& r3, uint32_t addr) {
    asm volatile("ldmatrix.sync.aligned.m8n8.x4.shared.b16 {%0,%1,%2,%3}, [%4];"
        : "=r"(r0), "=r"(r1), "=r"(r2), "=r"(r3) : "r"(addr));
}
__device__ __forceinline__ void mma_bf16(float* c, const uint32_t* a, const uint32_t* b) {
    asm volatile("mma.sync.aligned.m16n8k16.row.col.f32.bf16.bf16.f32 "
        "{%0,%1,%2,%3}, {%4,%5,%6,%7}, {%8,%9}, {%0,%1,%2,%3};"
        : "+f"(c[0]), "+f"(c[1]), "+f"(c[2]), "+f"(c[3])
        : "r"(a[0]), "r"(a[1]), "r"(a[2]), "r"(a[3]), "r"(b[0]), "r"(b[1]));
}
__device__ __forceinline__ void cp_async16(uint32_t saddr, const void* gptr) {
    asm volatile("cp.async.cg.shared.global [%0], [%1], 16;" :: "r"(saddr), "l"(gptr));
}
__device__ __forceinline__ void cp_commit() {
    asm volatile("cp.async.commit_group;");
}
template <int N>
__device__ __forceinline__ void cp_wait() {
    asm volatile("cp.async.wait_group %0;" :: "n"(N));
}
__device__ __forceinline__ void split1(float v, __nv_bfloat16& hi, __nv_bfloat16& lo) {
    hi = __float2bfloat16(v);
    lo = __float2bfloat16(v - __bfloat162float(hi));
}

// ---------------- dtype detection + edge index conversion ------------------
__global__ void detect_kernel(const int* __restrict__ ei32) {
    int t = threadIdx.x;
    int v = ei32[2 * t + 1];
    unsigned ok = __ballot_sync(0xffffffffu, v == 0);
    __shared__ int nz;
    if (t == 0) nz = 0;
    __syncthreads();
    if ((t & 31) == 0 && ok != 0xffffffffu) atomicAdd(&nz, 1);
    __syncthreads();
    if (t == 0) g_is64 = (nz == 0) ? 1 : 0;
}

__global__ void convert_kernel(const void* __restrict__ ei) {
    int i = blockIdx.x * blockDim.x + threadIdx.x;
    if (i < NN) g_deg[i] = 0;
    if (i >= 2 * EE) return;
    int v;
    if (g_is64) v = (int)((const long long*)ei)[i];
    else        v = ((const int*)ei)[i];
    if (i < EE) g_src[i] = v;
    else        g_dst[i - EE] = v;
}

__global__ void hist_kernel() {
    int e = blockIdx.x * blockDim.x + threadIdx.x;
    if (e < EE) atomicAdd(&g_deg[g_dst[e]], 1);
}

__global__ void blocksum_kernel() {
    int b = blockIdx.x * 256 + threadIdx.x;
    int d = (b < NN) ? g_deg[b] : 0;
#pragma unroll
    for (int o = 16; o > 0; o >>= 1) d += __shfl_xor_sync(0xffffffffu, d, o);
    __shared__ int ws[8];
    if ((threadIdx.x & 31) == 0) ws[threadIdx.x >> 5] = d;
    __syncthreads();
    if (threadIdx.x == 0) {
        int t = 0;
#pragma unroll
        for (int i = 0; i < 8; i++) t += ws[i];
        g_bsum[blockIdx.x] = t;
    }
}

__global__ void scanbsum_kernel() {
    __shared__ int s[512];
    int t = threadIdx.x;
    int v = (t < NB) ? g_bsum[t] : 0;
    s[t] = v;
    __syncthreads();
    for (int o = 1; o < 512; o <<= 1) {
        int a = (t >= o) ? s[t - o] : 0;
        __syncthreads();
        s[t] += a;
        __syncthreads();
    }
    g_bbase[t] = s[t] - v;
}

__global__ void binscan_kernel() {
    __shared__ int s[256];
    int t = threadIdx.x;
    int b = blockIdx.x * 256 + t;
    int d = (b < NN) ? g_deg[b] : 0;
    s[t] = d;
    __syncthreads();
    for (int o = 1; o < 256; o <<= 1) {
        int a = (t >= o) ? s[t - o] : 0;
        __syncthreads();
        s[t] += a;
        __syncthreads();
    }
    if (b < NN) {
        int off = g_bbase[blockIdx.x] + s[t] - d;
        g_off[b] = off;
        g_cur[b] = off;
    }
}

__global__ void scatter_kernel() {
    int e = blockIdx.x * blockDim.x + threadIdx.x;
    if (e >= EE) return;
    int d = g_dst[e];
    int pos = atomicAdd(&g_cur[d], 1);
    g_psrc[pos] = g_src[e];
}

// ---------------- W conversion: transpose + split ---------------------------
__global__ void conv_W(const float* __restrict__ Wl, const float* __restrict__ Wr) {
    int idx = blockIdx.x * 256 + threadIdx.x;   // 0..98303
    int m = idx >> 14;
    int r = idx & 16383;
    int k = r >> 7;
    int n = r & 127;
    int layer = m >> 1;
    const float* src = (m & 1) ? Wr : Wl;
    float v = src[layer * 16384 + k * 128 + n];
    __nv_bfloat16 hi, lo;
    split1(v, hi, lo);
    g_Bh[m][n * 128 + k] = hi;
    g_Bl[m][n * 128 + k] = lo;
}

// ---------------- x conversion (layer 0 A input) ---------------------------
__global__ void conv_x(const float* __restrict__ x) {
    int idx = blockIdx.x * blockDim.x + threadIdx.x;
    if (idx >= NN * 32) return;
    float4 v = ((const float4*)x)[idx];
    __nv_bfloat16 hx, hy, hz, hw, lx, ly, lz, lw;
    split1(v.x, hx, lx); split1(v.y, hy, ly);
    split1(v.z, hz, lz); split1(v.w, hw, lw);
    __nv_bfloat162* ph = (__nv_bfloat162*)g_Ah + idx * 2;
    __nv_bfloat162* pl = (__nv_bfloat162*)g_Al + idx * 2;
    ph[0] = __nv_bfloat162(hx, hy); ph[1] = __nv_bfloat162(hz, hw);
    pl[0] = __nv_bfloat162(lx, ly); pl[1] = __nv_bfloat162(lz, lw);
}

// ---------------- tensor-core GEMM: cp.async double-buffered pipeline ------
// CTA tile 128x128. K chunked 4x32; per-buffer = AH|AL|BH|BL each 128x(80B row)
// = 10240 B -> 40960 B/buffer, 2 buffers = 81920 B, 2 CTA/SM.
#define CROW 80
#define SEG 10240
#define BUFSZ 40960
#define GEMM_SMEM 81920

__global__ void __launch_bounds__(256, 2) gemm_mma(int layer) {
    extern __shared__ char smem[];
    const int tid = threadIdx.x;
    const int wid = tid >> 5;
    const int lane = tid & 31;
    const int rowBase = blockIdx.x * 128;
    const int mat = layer * 2 + blockIdx.y;

    const int m0 = (wid >> 2) * 64;
    const int n0 = (wid & 3) * 32;

    float acc[4][4][4];
#pragma unroll
    for (int i = 0; i < 4; i++)
#pragma unroll
        for (int j = 0; j < 4; j++)
#pragma unroll
            for (int q = 0; q < 4; q++) acc[i][j][q] = 0.0f;

    const uint32_t sbase = smem_u32(smem);
    const uint32_t a_row = m0 + (lane & 15);
    const uint32_t a_coff = ((lane >> 4) << 4);     // 0 or 16 bytes
    const int quad = lane >> 3;
    const uint32_t b_row = n0 + ((quad >> 1) << 3) + (lane & 7);
    const uint32_t b_coff = ((quad & 1) << 4);      // 0 or 16 bytes

    const char* aHg = (const char*)g_Ah;
    const char* aLg = (const char*)g_Al;
    const char* bHg = (const char*)g_Bh[mat];
    const char* bLg = (const char*)g_Bl[mat];

    // per-thread load assignment: 8 of 2048 ops per chunk
    // op o: seg = o>>9 (AH,AL,BH,BL), r = (o>>2)&127, j = o&3
    auto load_chunk = [&](int kc, int buf) {
        uint32_t sb = sbase + buf * BUFSZ;
#pragma unroll
        for (int p = 0; p < 8; p++) {
            int o = tid + p * 256;
            int seg = o >> 9;
            int r = (o >> 2) & 127;
            int j = o & 3;
            uint32_t saddr = sb + seg * SEG + r * CROW + j * 16;
            const char* g;
            if (seg == 0)      g = aHg + ((rowBase + r) * 256 + kc * 64 + j * 16);
            else if (seg == 1) g = aLg + ((rowBase + r) * 256 + kc * 64 + j * 16);
            else if (seg == 2) g = bHg + (r * 256 + kc * 64 + j * 16);
            else               g = bLg + (r * 256 + kc * 64 + j * 16);
            cp_async16(saddr, g);
        }
        cp_commit();
    };

    load_chunk(0, 0);

#pragma unroll
    for (int kc = 0; kc < 4; kc++) {
        if (kc < 3) load_chunk(kc + 1, (kc + 1) & 1);
        if (kc < 3) cp_wait<1>(); else cp_wait<0>();
        __syncthreads();

        const uint32_t sb = sbase + (kc & 1) * BUFSZ;
#pragma unroll
        for (int ks = 0; ks < 2; ks++) {
            const uint32_t k0b = ks * 32;
            uint32_t bHf[4][2], bLf[4][2];
#pragma unroll
            for (int p = 0; p < 2; p++) {
                uint32_t bd = sb + 2 * SEG + (b_row + p * 16) * CROW + k0b + b_coff;
                uint32_t r0, r1, r2, r3;
                ldmatrix_x4(r0, r1, r2, r3, bd);
                bHf[p * 2][0] = r0; bHf[p * 2][1] = r1;
                bHf[p * 2 + 1][0] = r2; bHf[p * 2 + 1][1] = r3;
                ldmatrix_x4(r0, r1, r2, r3, bd + SEG);
                bLf[p * 2][0] = r0; bLf[p * 2][1] = r1;
                bLf[p * 2 + 1][0] = r2; bLf[p * 2 + 1][1] = r3;
            }
#pragma unroll
            for (int mi = 0; mi < 4; mi++) {
                uint32_t aHf[4], aLf[4];
                uint32_t ad = sb + (a_row + mi * 16) * CROW + k0b + a_coff;
                ldmatrix_x4(aHf[0], aHf[1], aHf[2], aHf[3], ad);
                ldmatrix_x4(aLf[0], aLf[1], aLf[2], aLf[3], ad + SEG);
#pragma unroll
                for (int ni = 0; ni < 4; ni++) {
                    mma_bf16(acc[mi][ni], aHf, bHf[ni]);
                    mma_bf16(acc[mi][ni], aLf, bHf[ni]);
                    mma_bf16(acc[mi][ni], aHf, bLf[ni]);
                }
            }
        }
        __syncthreads();
    }

    float* __restrict__ C = (blockIdx.y == 0) ? g_xl : g_xr;
#pragma unroll
    for (int mi = 0; mi < 4; mi++) {
#pragma unroll
        for (int ni = 0; ni < 4; ni++) {
            int row0 = rowBase + m0 + mi * 16 + (lane >> 2);
            int col = n0 + ni * 8 + (lane & 3) * 2;
            if (row0 < NN)
                *(float2*)&C[row0 * 128 + col] = make_float2(acc[mi][ni][0], acc[mi][ni][1]);
            int row1 = row0 + 8;
            if (row1 < NN)
                *(float2*)&C[row1 * 128 + col] = make_float2(acc[mi][ni][2], acc[mi][ni][3]);
        }
    }
}

// ---------------- fused node kernel: online softmax aggregation -----------
__device__ __forceinline__ void edge_update(
    float4 v, float pe, float& m, float& ssum, float4& acc)
{
    float mn = fmaxf(m, pe);
    float corr = __expf(m - mn);
    float wgt  = __expf(pe - mn);
    ssum = ssum * corr + wgt;
    acc.x = acc.x * corr + wgt * v.x;
    acc.y = acc.y * corr + wgt * v.y;
    acc.z = acc.z * corr + wgt * v.z;
    acc.w = acc.w * corr + wgt * v.w;
    m = mn;
}

__global__ void __launch_bounds__(256) node_fused(
    const float* __restrict__ att,
    const float* __restrict__ bias,
    float* __restrict__ outp, int sel)
{
    int warp = (blockIdx.x * blockDim.x + threadIdx.x) >> 5;
    int lane = threadIdx.x & 31;
    if (warp >= NN) return;
    const int n = warp;

    float4 xr4 = *(const float4*)&g_xr[(long long)n * 128 + lane * 4];
    float4 w4  = *(const float4*)&att[lane * 4];

    int beg = g_off[n];
    int end = beg + g_deg[n];

    float m = -CUDART_INF_F;
    float ssum = 0.0f;
    float4 acc = make_float4(0.f, 0.f, 0.f, 0.f);

    int i = beg;
    for (; i + 3 < end; i += 4) {
        int s0 = g_psrc[i], s1 = g_psrc[i + 1], s2 = g_psrc[i + 2], s3 = g_psrc[i + 3];
        float4 v0 = *(const float4*)&g_xl[(long long)s0 * 128 + lane * 4];
        float4 v1 = *(const float4*)&g_xl[(long long)s1 * 128 + lane * 4];
        float4 v2 = *(const float4*)&g_xl[(long long)s2 * 128 + lane * 4];
        float4 v3 = *(const float4*)&g_xl[(long long)s3 * 128 + lane * 4];
        float p0, p1, p2, p3;
        {
            float z;
            z = v0.x + xr4.x; z = (z > 0.f) ? z : NEG_SLOPE * z; p0 = z * w4.x;
            z = v0.y + xr4.y; z = (z > 0.f) ? z : NEG_SLOPE * z; p0 += z * w4.y;
            z = v0.z + xr4.z; z = (z > 0.f) ? z : NEG_SLOPE * z; p0 += z * w4.z;
            z = v0.w + xr4.w; z = (z > 0.f) ? z : NEG_SLOPE * z; p0 += z * w4.w;
            z = v1.x + xr4.x; z = (z > 0.f) ? z : NEG_SLOPE * z; p1 = z * w4.x;
            z = v1.y + xr4.y; z = (z > 0.f) ? z : NEG_SLOPE * z; p1 += z * w4.y;
            z = v1.z + xr4.z; z = (z > 0.f) ? z : NEG_SLOPE * z; p1 += z * w4.z;
            z = v1.w + xr4.w; z = (z > 0.f) ? z : NEG_SLOPE * z; p1 += z * w4.w;
            z = v2.x + xr4.x; z = (z > 0.f) ? z : NEG_SLOPE * z; p2 = z * w4.x;
            z = v2.y + xr4.y; z = (z > 0.f) ? z : NEG_SLOPE * z; p2 += z * w4.y;
            z = v2.z + xr4.z; z = (z > 0.f) ? z : NEG_SLOPE * z; p2 += z * w4.z;
            z = v2.w + xr4.w; z = (z > 0.f) ? z : NEG_SLOPE * z; p2 += z * w4.w;
            z = v3.x + xr4.x; z = (z > 0.f) ? z : NEG_SLOPE * z; p3 = z * w4.x;
            z = v3.y + xr4.y; z = (z > 0.f) ? z : NEG_SLOPE * z; p3 += z * w4.y;
            z = v3.z + xr4.z; z = (z > 0.f) ? z : NEG_SLOPE * z; p3 += z * w4.z;
            z = v3.w + xr4.w; z = (z > 0.f) ? z : NEG_SLOPE * z; p3 += z * w4.w;
        }
#pragma unroll
        for (int o = 16; o > 0; o >>= 1) {
            p0 += __shfl_xor_sync(0xffffffffu, p0, o);
            p1 += __shfl_xor_sync(0xffffffffu, p1, o);
            p2 += __shfl_xor_sync(0xffffffffu, p2, o);
            p3 += __shfl_xor_sync(0xffffffffu, p3, o);
        }
        edge_update(v0, p0, m, ssum, acc);
        edge_update(v1, p1, m, ssum, acc);
        edge_update(v2, p2, m, ssum, acc);
        edge_update(v3, p3, m, ssum, acc);
    }
    for (; i < end; i++) {
        int s = g_psrc[i];
        float4 v = *(const float4*)&g_xl[(long long)s * 128 + lane * 4];
        float z, pe;
        z = v.x + xr4.x; z = (z > 0.f) ? z : NEG_SLOPE * z; pe = z * w4.x;
        z = v.y + xr4.y; z = (z > 0.f) ? z : NEG_SLOPE * z; pe += z * w4.y;
        z = v.z + xr4.z; z = (z > 0.f) ? z : NEG_SLOPE * z; pe += z * w4.z;
        z = v.w + xr4.w; z = (z > 0.f) ? z : NEG_SLOPE * z; pe += z * w4.w;
#pragma unroll
        for (int o = 16; o > 0; o >>= 1) pe += __shfl_xor_sync(0xffffffffu, pe, o);
        edge_update(v, pe, m, ssum, acc);
    }

    float inv = 1.0f / (ssum + 1e-16f);
    float4 b4 = *(const float4*)&bias[lane * 4];
    float4 o;
    o.x = acc.x * inv + b4.x;
    o.y = acc.y * inv + b4.y;
    o.z = acc.z * inv + b4.z;
    o.w = acc.w * inv + b4.w;

    if (sel == 2) {
        *(float4*)&outp[(long long)n * 128 + lane * 4] = o;
    } else {
        o.x = fmaxf(o.x, 0.f); o.y = fmaxf(o.y, 0.f);
        o.z = fmaxf(o.z, 0.f); o.w = fmaxf(o.w, 0.f);
        __nv_bfloat16 hx, hy, hz, hw, lx, ly, lz, lw;
        split1(o.x, hx, lx); split1(o.y, hy, ly);
        split1(o.z, hz, lz); split1(o.w, hw, lw);
        __nv_bfloat162* ph = (__nv_bfloat162*)&g_Ah[n * 128 + lane * 4];
        __nv_bfloat162* pl = (__nv_bfloat162*)&g_Al[n * 128 + lane * 4];
        ph[0] = __nv_bfloat162(hx, hy); ph[1] = __nv_bfloat162(hz, hw);
        pl[0] = __nv_bfloat162(lx, ly); pl[1] = __nv_bfloat162(lz, lw);
    }
}

// ---------------- host ------------------------------------------------------
extern "C" void kernel_launch(void* const* d_in, const int* in_sizes, int n_in,
                              void* d_out, int out_size)
{
    const float* x   = (const float*)d_in[0];
    const float* Wl  = (const float*)d_in[1];
    const float* Wr  = (const float*)d_in[2];
    const float* att = (const float*)d_in[3];
    const float* b   = (const float*)d_in[4];
    const void*  ei  = d_in[5];
    float* outp = (float*)d_out;

    cudaFuncSetAttribute(gemm_mma, cudaFuncAttributeMaxDynamicSharedMemorySize, GEMM_SMEM);

    dim3 gemmGrid(NPAD / 128, 2);
    int nodeBlocks = (NN * 32 + 255) / 256;

    // gemm_mma(layer0) at my index 3 -> absolute ncu index 5 (offset +2
    // calibrated from R3/R6 captures), so next profile shows the GEMM.
    conv_W<<<384, 256>>>(Wl, Wr);                          // 0
    conv_x<<<(NN * 32 + 255) / 256, 256>>>(x);             // 1
    detect_kernel<<<1, 256>>>((const int*)ei);             // 2
    gemm_mma<<<gemmGrid, 256, GEMM_SMEM>>>(0);             // 3  <- profiled
    convert_kernel<<<(2 * EE + 255) / 256, 256>>>(ei);     // 4
    hist_kernel<<<(EE + 255) / 256, 256>>>();              // 5
    blocksum_kernel<<<NB, 256>>>();                        // 6
    scanbsum_kernel<<<1, 512>>>();                         // 7
    binscan_kernel<<<NB, 256>>>();                         // 8
    scatter_kernel<<<(EE + 255) / 256, 256>>>();           // 9
    node_fused<<<nodeBlocks, 256>>>(att, b, outp, 0);      // 10

    for (int layer = 1; layer < 3; layer++) {
        gemm_mma<<<gemmGrid, 256, GEMM_SMEM>>>(layer);
        node_fused<<<nodeBlocks, 256>>>(att + layer * DD, b + layer * DD, outp, layer);
    }
}